// round 13
// baseline (speedup 1.0000x reference)
#include <cuda_runtime.h>
#include <cuda_bf16.h>
#include <cuda_fp16.h>
#include <mma.h>
#include <cstdint>
#include <type_traits>

using namespace nvcuda;

#define Bq 2
#define Sq 2048
#define Eq 1024
#define Hq 16
#define Dq 64

// Scratch buffers (no cudaMalloc allowed)
__device__ __half g_qkv[(size_t)Bq * Sq * 3 * Eq];    // [B*S, 3E] fp16 (RoPE'd)
__device__ __half g_attn[(size_t)Bq * Sq * Eq];       // [B*S, E] fp16
__device__ __half g_xh[(size_t)Bq * Sq * Eq];         // fp16 x
__device__ __half g_wqkvh[(size_t)Eq * 3 * Eq];       // fp16 w_qkv
__device__ __half g_wouth[(size_t)Eq * Eq];           // fp16 w_out

// ---------------------------------------------------------------------------
// helpers
// ---------------------------------------------------------------------------
__device__ __forceinline__ void cp16(void* dst_smem, const void* src) {
    unsigned int d = (unsigned int)__cvta_generic_to_shared(dst_smem);
    asm volatile("cp.async.cg.shared.global [%0], [%1], 16;\n" :: "r"(d), "l"(src));
}
__device__ __forceinline__ void cp_commit() {
    asm volatile("cp.async.commit_group;\n");
}
template <int N> __device__ __forceinline__ void cp_wait() {
    asm volatile("cp.async.wait_group %0;\n" :: "n"(N));
}

// mma m16n8k16 fp16 inputs, f32 accum
__device__ __forceinline__ void mma_f16(float* d, const uint32_t* a,
                                        uint32_t b0, uint32_t b1) {
    asm volatile(
        "mma.sync.aligned.m16n8k16.row.col.f32.f16.f16.f32 "
        "{%0,%1,%2,%3}, {%4,%5,%6,%7}, {%8,%9}, {%0,%1,%2,%3};\n"
        : "+f"(d[0]), "+f"(d[1]), "+f"(d[2]), "+f"(d[3])
        : "r"(a[0]), "r"(a[1]), "r"(a[2]), "r"(a[3]), "r"(b0), "r"(b1));
}

__device__ __forceinline__ void ldsm_x4_trans(unsigned int addr,
    uint32_t& r0, uint32_t& r1, uint32_t& r2, uint32_t& r3) {
    asm volatile(
        "ldmatrix.sync.aligned.m8n8.x4.trans.shared.b16 {%0,%1,%2,%3}, [%4];\n"
        : "=r"(r0), "=r"(r1), "=r"(r2), "=r"(r3) : "r"(addr));
}

__device__ __forceinline__ uint32_t packh2(float lo, float hi) {
    __half2 h = __floats2half2_rn(lo, hi);
    return *(uint32_t*)&h;
}

// ---------------------------------------------------------------------------
// Elementwise f32 -> f16 conversion pass
// ---------------------------------------------------------------------------
__global__ void f32_to_f16_kernel(const float* __restrict__ src,
                                  __half* __restrict__ dst, int n4)
{
    int i = blockIdx.x * blockDim.x + threadIdx.x;
    if (i < n4) {
        float4 v = ((const float4*)src)[i];
        ((__half2*)dst)[2 * i]     = __floats2half2_rn(v.x, v.y);
        ((__half2*)dst)[2 * i + 1] = __floats2half2_rn(v.z, v.w);
    }
}

// ---------------------------------------------------------------------------
// FP16 GEMM (f32 accum): 128x128x32 block, 256 threads = 8 warps,
// warp grid 2(M)x4(N), 64x32 warp tile (R10 topology: 16 warps/SM).
// cp.async 3-stage pipeline.
// DoRope: fuse RoPE (Q pre-scaled by 0.125, K rotated) into fp16 epilogue.
// ---------------------------------------------------------------------------
#define GT_M 128
#define GT_N 128
#define GT_K 32
#define A_LDH 40
#define B_LDH 136
#define GA_SZ (GT_M * A_LDH)
#define GB_SZ (GT_K * B_LDH)
#define STAGE_SZ (GA_SZ + GB_SZ)
#define G_STAGES 3
#define GEMM_SMEM (G_STAGES * STAGE_SZ * sizeof(__half))   // 56832 B
#define C_STAGE_LD 20

template <typename OutT, bool DoRope>
__global__ __launch_bounds__(256, 2) void gemm_f16(
    const __half* __restrict__ A, const __half* __restrict__ B,
    OutT* __restrict__ C, int M, int N, int K,
    const float* __restrict__ fcos, const float* __restrict__ fsin)
{
    extern __shared__ __half gsm[];

    const int tid = threadIdx.x;
    const int warp = tid >> 5;
    const int lane = tid & 31;
    const int wm = warp & 1;          // 64-row slab
    const int wn = warp >> 1;         // 32-col slab
    const int brow = blockIdx.y * GT_M;
    const int bcol = blockIdx.x * GT_N;

    const int arw = tid >> 2;
    const int ac8 = (tid & 3) * 8;
    const int brw = tid >> 4;
    const int bc8 = (tid & 15) * 8;

    wmma::fragment<wmma::accumulator, 16, 16, 16, float> c[4][2];
#pragma unroll
    for (int i = 0; i < 4; i++)
#pragma unroll
        for (int j = 0; j < 2; j++) wmma::fill_fragment(c[i][j], 0.f);

    const int T = K / GT_K;

    auto issue = [&](int t) {
        __half* dst = gsm + (t % G_STAGES) * STAGE_SZ;
        int k0 = t * GT_K;
#pragma unroll
        for (int p = 0; p < 2; p++)
            cp16(&dst[(arw + p * 64) * A_LDH + ac8],
                 &A[(size_t)(brow + arw + p * 64) * K + k0 + ac8]);
#pragma unroll
        for (int p = 0; p < 2; p++)
            cp16(&dst[GA_SZ + (brw + p * 16) * B_LDH + bc8],
                 &B[(size_t)(k0 + brw + p * 16) * N + bcol + bc8]);
        cp_commit();
    };

    issue(0);
    issue(1);

    for (int t = 0; t < T; t++) {
        cp_wait<G_STAGES - 2>();
        __syncthreads();

        if (t + G_STAGES - 1 < T) issue(t + G_STAGES - 1);

        __half* Ac = gsm + (t % G_STAGES) * STAGE_SZ;
        __half* Bc = Ac + GA_SZ;
#pragma unroll
        for (int kk = 0; kk < GT_K; kk += 16) {
            wmma::fragment<wmma::matrix_a, 16, 16, 16, __half, wmma::row_major> a[4];
            wmma::fragment<wmma::matrix_b, 16, 16, 16, __half, wmma::row_major> bf[2];
#pragma unroll
            for (int i = 0; i < 4; i++)
                wmma::load_matrix_sync(a[i], &Ac[(wm * 64 + i * 16) * A_LDH + kk], A_LDH);
#pragma unroll
            for (int j = 0; j < 2; j++)
                wmma::load_matrix_sync(bf[j], &Bc[kk * B_LDH + wn * 32 + j * 16], B_LDH);
#pragma unroll
            for (int i = 0; i < 4; i++)
#pragma unroll
                for (int j = 0; j < 2; j++)
                    wmma::mma_sync(c[i][j], a[i], bf[j], c[i][j]);
        }
        __syncthreads();
    }

    if constexpr (std::is_same<OutT, float>::value) {
#pragma unroll
        for (int i = 0; i < 4; i++)
#pragma unroll
            for (int j = 0; j < 2; j++)
                wmma::store_matrix_sync(
                    &C[(size_t)(brow + wm * 64 + i * 16) * N + bcol + wn * 32 + j * 16],
                    c[i][j], N, wmma::mem_row_major);
    } else {
        // stage f32 c-frags through smem, optionally apply RoPE, emit fp16
        float* stage = (float*)gsm + warp * (16 * C_STAGE_LD);
        const int r = lane >> 1;
        const int c0 = (lane & 1) * 8;
#pragma unroll
        for (int i = 0; i < 4; i++)
#pragma unroll
            for (int j = 0; j < 2; j++) {
                wmma::store_matrix_sync(stage, c[i][j], C_STAGE_LD,
                                        wmma::mem_row_major);
                __syncwarp();
                const float* sp = stage + r * C_STAGE_LD + c0;
                const int row_g = brow + wm * 64 + i * 16 + r;
                const int col_g = bcol + wn * 32 + j * 16 + c0;
                __half2 h[4];
                if (DoRope && col_g < 2 * Eq) {
                    // fragment columns never straddle head/QKV boundaries
                    const int s = row_g & (Sq - 1);
                    const float scl = (col_g < Eq) ? 0.125f : 1.f;
                    const int pr0 = (col_g & 63) >> 1;
#pragma unroll
                    for (int q = 0; q < 4; q++) {
                        float cc = fcos[s * 32 + pr0 + q];
                        float sn = fsin[s * 32 + pr0 + q];
                        float x0 = sp[2 * q], x1 = sp[2 * q + 1];
                        h[q] = __floats2half2_rn((x0 * cc - x1 * sn) * scl,
                                                 (x0 * sn + x1 * cc) * scl);
                    }
                } else {
#pragma unroll
                    for (int q = 0; q < 4; q++)
                        h[q] = __floats2half2_rn(sp[2 * q], sp[2 * q + 1]);
                }
                *(uint4*)&C[(size_t)row_g * N + col_g] = *(uint4*)h;
                __syncwarp();
            }
    }
}

// ---------------------------------------------------------------------------
// Register-resident flash attention, fp16 mma m16n8k16 (unchanged from R11).
// Q/K already RoPE'd in gmem; K/V fills pure cp.async, double-buffered.
// ---------------------------------------------------------------------------
#define QLDH 72
#define KLDH 72
#define VLDH 72
#define KV_SZ (64 * KLDH)
#define FA_SMEM (4 * KV_SZ * sizeof(__half))   // 36864 B

__global__ __launch_bounds__(256, 2) void flash_attn_f16(
    const __half* __restrict__ qkv,
    __half* __restrict__ attn)
{
    extern __shared__ __half smh[];
    __half* Qstage = smh;

    const int tid  = threadIdx.x;
    const int lane = tid & 31;
    const int wr   = tid >> 5;
    const int g    = lane >> 2;
    const int j    = lane & 3;
    const int qi   = blockIdx.x;
    const int b    = blockIdx.y >> 4;
    const int h    = blockIdx.y & 15;
    const int qbase = qi * 128;
    const size_t rs3 = 3 * Eq;
    const size_t base = (size_t)b * Sq * rs3 + (size_t)h * Dq;

    for (int t = tid; t < 128 * 8; t += 256) {
        int r = t >> 3, c8 = (t & 7) * 8;
        *(uint4*)&Qstage[r * QLDH + c8] =
            *(const uint4*)&qkv[base + (size_t)(qbase + r) * rs3 + c8];
    }
    __syncthreads();

    uint32_t qa[4][4];
    {
        const int r0 = wr * 16 + g;
#pragma unroll
        for (int kc = 0; kc < 4; kc++) {
            int col = kc * 16 + 2 * j;
            qa[kc][0] = *(const uint32_t*)&Qstage[r0 * QLDH + col];
            qa[kc][1] = *(const uint32_t*)&Qstage[(r0 + 8) * QLDH + col];
            qa[kc][2] = *(const uint32_t*)&Qstage[r0 * QLDH + col + 8];
            qa[kc][3] = *(const uint32_t*)&Qstage[(r0 + 8) * QLDH + col + 8];
        }
    }
    __syncthreads();

    float od[8][4];
#pragma unroll
    for (int n = 0; n < 8; n++)
#pragma unroll
        for (int i = 0; i < 4; i++) od[n][i] = 0.f;

    float m0 = -1e30f, m1 = -1e30f, l0 = 0.f, l1 = 0.f;

    const int wq_lo = qbase + wr * 16;
    const int wq_hi = wq_lo + 15;
    const int r0g = wq_lo + g;
    const int r1g = r0g + 8;
    const int ntiles = 2 * qi + 2;

    const int lm_m  = lane >> 3;
    const int lm_rr = lane & 7;
    const int lm_keyoff = (lm_m & 1) * 8 + lm_rr;
    const int lm_dimoff = (lm_m >> 1) * 8;

    auto issue_tile = [&](int kt) {
        __half* kd = smh + (kt & 1) * 2 * KV_SZ;
        __half* vd = kd + KV_SZ;
        const int kb = kt * 64;
#pragma unroll
        for (int p = 0; p < 2; p++) {
            int t = tid + p * 256;
            int r = t >> 3, c8 = (t & 7) * 8;
            cp16(&kd[r * KLDH + c8],
                 &qkv[base + Eq + (size_t)(kb + r) * rs3 + c8]);
        }
#pragma unroll
        for (int p = 0; p < 2; p++) {
            int t = tid + p * 256;
            int r = t >> 3, c8 = (t & 7) * 8;
            cp16(&vd[r * VLDH + c8],
                 &qkv[base + 2 * Eq + (size_t)(kb + r) * rs3 + c8]);
        }
        cp_commit();
    };

    issue_tile(0);

    for (int kt = 0; kt < ntiles; ++kt) {
        if (kt + 1 < ntiles) {
            issue_tile(kt + 1);
            cp_wait<1>();
        } else {
            cp_wait<0>();
        }
        __syncthreads();

        const __half* Ks = smh + (kt & 1) * 2 * KV_SZ;
        const __half* Vs = Ks + KV_SZ;
        const int kbase = kt * 64;

        if (kbase <= wq_hi) {
            float s[8][4];
#pragma unroll
            for (int nc = 0; nc < 8; nc++) {
                s[nc][0] = s[nc][1] = s[nc][2] = s[nc][3] = 0.f;
                const __half* krow = &Ks[(nc * 8 + g) * KLDH + 2 * j];
#pragma unroll
                for (int kc = 0; kc < 4; kc++) {
                    uint32_t kb0 = *(const uint32_t*)&krow[kc * 16];
                    uint32_t kb1 = *(const uint32_t*)&krow[kc * 16 + 8];
                    mma_f16(s[nc], qa[kc], kb0, kb1);
                }
            }

            if (kbase + 63 > wq_lo) {
#pragma unroll
                for (int nc = 0; nc < 8; nc++) {
                    int c0 = kbase + nc * 8 + 2 * j;
                    if (c0 > r0g)     s[nc][0] = -1e30f;
                    if (c0 + 1 > r0g) s[nc][1] = -1e30f;
                    if (c0 > r1g)     s[nc][2] = -1e30f;
                    if (c0 + 1 > r1g) s[nc][3] = -1e30f;
                }
            }

            float mx0 = -1e30f, mx1 = -1e30f;
#pragma unroll
            for (int nc = 0; nc < 8; nc++) {
                mx0 = fmaxf(mx0, fmaxf(s[nc][0], s[nc][1]));
                mx1 = fmaxf(mx1, fmaxf(s[nc][2], s[nc][3]));
            }
            mx0 = fmaxf(mx0, __shfl_xor_sync(0xffffffffu, mx0, 1));
            mx0 = fmaxf(mx0, __shfl_xor_sync(0xffffffffu, mx0, 2));
            mx1 = fmaxf(mx1, __shfl_xor_sync(0xffffffffu, mx1, 1));
            mx1 = fmaxf(mx1, __shfl_xor_sync(0xffffffffu, mx1, 2));

            float mn0 = fmaxf(m0, mx0);
            float mn1 = fmaxf(m1, mx1);
            float corr0 = __expf(m0 - mn0);
            float corr1 = __expf(m1 - mn1);
            m0 = mn0; m1 = mn1;

            float sum0 = 0.f, sum1 = 0.f;
#pragma unroll
            for (int nc = 0; nc < 8; nc++) {
                s[nc][0] = __expf(s[nc][0] - mn0);
                s[nc][1] = __expf(s[nc][1] - mn0);
                s[nc][2] = __expf(s[nc][2] - mn1);
                s[nc][3] = __expf(s[nc][3] - mn1);
                sum0 += s[nc][0] + s[nc][1];
                sum1 += s[nc][2] + s[nc][3];
            }
            sum0 += __shfl_xor_sync(0xffffffffu, sum0, 1);
            sum0 += __shfl_xor_sync(0xffffffffu, sum0, 2);
            sum1 += __shfl_xor_sync(0xffffffffu, sum1, 1);
            sum1 += __shfl_xor_sync(0xffffffffu, sum1, 2);
            l0 = l0 * corr0 + sum0;
            l1 = l1 * corr1 + sum1;

#pragma unroll
            for (int n = 0; n < 8; n++) {
                od[n][0] *= corr0; od[n][1] *= corr0;
                od[n][2] *= corr1; od[n][3] *= corr1;
            }

            uint32_t pa[4][4];
#pragma unroll
            for (int kc = 0; kc < 4; kc++) {
                pa[kc][0] = packh2(s[2 * kc][0],     s[2 * kc][1]);
                pa[kc][1] = packh2(s[2 * kc][2],     s[2 * kc][3]);
                pa[kc][2] = packh2(s[2 * kc + 1][0], s[2 * kc + 1][1]);
                pa[kc][3] = packh2(s[2 * kc + 1][2], s[2 * kc + 1][3]);
            }

#pragma unroll
            for (int nd2 = 0; nd2 < 4; nd2++) {
#pragma unroll
                for (int kc = 0; kc < 4; kc++) {
                    unsigned int addr = (unsigned int)__cvta_generic_to_shared(
                        &Vs[(kc * 16 + lm_keyoff) * VLDH + nd2 * 16 + lm_dimoff]);
                    uint32_t b0, b1, b2, b3;
                    ldsm_x4_trans(addr, b0, b1, b2, b3);
                    mma_f16(od[2 * nd2],     pa[kc], b0, b1);
                    mma_f16(od[2 * nd2 + 1], pa[kc], b2, b3);
                }
            }
        }
        __syncthreads();
    }

    {
        float inv0 = 1.f / l0;
        float inv1 = 1.f / l1;
        __half* op0 = &attn[((size_t)b * Sq + r0g) * Eq + h * Dq];
        __half* op1 = &attn[((size_t)b * Sq + r1g) * Eq + h * Dq];
#pragma unroll
        for (int nd = 0; nd < 8; nd++) {
            int c0 = nd * 8 + 2 * j;
            *(__half2*)&op0[c0] = __floats2half2_rn(od[nd][0] * inv0, od[nd][1] * inv0);
            *(__half2*)&op1[c0] = __floats2half2_rn(od[nd][2] * inv1, od[nd][3] * inv1);
        }
    }
}

// ---------------------------------------------------------------------------
extern "C" void kernel_launch(void* const* d_in, const int* in_sizes, int n_in,
                              void* d_out, int out_size)
{
    const float* x     = (const float*)d_in[0];
    const float* w_qkv = (const float*)d_in[1];
    const float* w_out = (const float*)d_in[2];
    const float* fcos  = (const float*)d_in[3];
    const float* fsin  = (const float*)d_in[4];
    float* out = (float*)d_out;

    __half *qkv, *attn, *xh, *wqkvh, *wouth;
    cudaGetSymbolAddress((void**)&qkv, g_qkv);
    cudaGetSymbolAddress((void**)&attn, g_attn);
    cudaGetSymbolAddress((void**)&xh, g_xh);
    cudaGetSymbolAddress((void**)&wqkvh, g_wqkvh);
    cudaGetSymbolAddress((void**)&wouth, g_wouth);

    cudaFuncSetAttribute((const void*)gemm_f16<__half, true>,
                         cudaFuncAttributeMaxDynamicSharedMemorySize, GEMM_SMEM);
    cudaFuncSetAttribute((const void*)gemm_f16<float, false>,
                         cudaFuncAttributeMaxDynamicSharedMemorySize, GEMM_SMEM);
    cudaFuncSetAttribute(flash_attn_f16,
                         cudaFuncAttributeMaxDynamicSharedMemorySize, FA_SMEM);

    // 0) fp16 conversion of GEMM inputs
    {
        int n4x = Bq * Sq * Eq / 4;
        int n4q = Eq * 3 * Eq / 4;
        int n4o = Eq * Eq / 4;
        f32_to_f16_kernel<<<(n4x + 255) / 256, 256>>>(x, xh, n4x);
        f32_to_f16_kernel<<<(n4q + 255) / 256, 256>>>(w_qkv, wqkvh, n4q);
        f32_to_f16_kernel<<<(n4o + 255) / 256, 256>>>(w_out, wouth, n4o);
    }

    // 1) QKV projection -> fp16 qkv with fused RoPE (Q pre-scaled, K rotated)
    gemm_f16<__half, true><<<dim3(3 * Eq / GT_N, Bq * Sq / GT_M), 256, GEMM_SMEM>>>(
        xh, wqkvh, qkv, Bq * Sq, 3 * Eq, Eq, fcos, fsin);

    // 2) causal flash attention (fp16 mma, double-buffered cp.async K/V)
    flash_attn_f16<<<dim3(Sq / 128, Bq * Hq), 256, FA_SMEM>>>(qkv, attn);

    // 3) output projection -> fp32 out
    gemm_f16<float, false><<<dim3(Eq / GT_N, Bq * Sq / GT_M), 256, GEMM_SMEM>>>(
        attn, wouth, out, Bq * Sq, Eq, Eq, nullptr, nullptr);
}

// round 14
// speedup vs baseline: 1.0603x; 1.0603x over previous
#include <cuda_runtime.h>
#include <cuda_bf16.h>
#include <cuda_fp16.h>
#include <mma.h>
#include <cstdint>
#include <type_traits>

using namespace nvcuda;

#define Bq 2
#define Sq 2048
#define Eq 1024
#define Hq 16
#define Dq 64

// Scratch buffers (no cudaMalloc allowed)
__device__ __half g_qkv[(size_t)Bq * Sq * 3 * Eq];    // [B*S, 3E] fp16 (RoPE'd)
__device__ __half g_attn[(size_t)Bq * Sq * Eq];       // [B*S, E] fp16
__device__ __half g_xh[(size_t)Bq * Sq * Eq];         // fp16 x
__device__ __half g_wqkvh[(size_t)Eq * 3 * Eq];       // fp16 w_qkv
__device__ __half g_wouth[(size_t)Eq * Eq];           // fp16 w_out

// ---------------------------------------------------------------------------
// helpers
// ---------------------------------------------------------------------------
__device__ __forceinline__ void cp16(void* dst_smem, const void* src) {
    unsigned int d = (unsigned int)__cvta_generic_to_shared(dst_smem);
    asm volatile("cp.async.cg.shared.global [%0], [%1], 16;\n" :: "r"(d), "l"(src));
}
__device__ __forceinline__ void cp_commit() {
    asm volatile("cp.async.commit_group;\n");
}
template <int N> __device__ __forceinline__ void cp_wait() {
    asm volatile("cp.async.wait_group %0;\n" :: "n"(N));
}

// mma m16n8k16 fp16 inputs, f32 accum
__device__ __forceinline__ void mma_f16(float* d, const uint32_t* a,
                                        uint32_t b0, uint32_t b1) {
    asm volatile(
        "mma.sync.aligned.m16n8k16.row.col.f32.f16.f16.f32 "
        "{%0,%1,%2,%3}, {%4,%5,%6,%7}, {%8,%9}, {%0,%1,%2,%3};\n"
        : "+f"(d[0]), "+f"(d[1]), "+f"(d[2]), "+f"(d[3])
        : "r"(a[0]), "r"(a[1]), "r"(a[2]), "r"(a[3]), "r"(b0), "r"(b1));
}

__device__ __forceinline__ void ldsm_x4(unsigned int addr,
    uint32_t& r0, uint32_t& r1, uint32_t& r2, uint32_t& r3) {
    asm volatile(
        "ldmatrix.sync.aligned.m8n8.x4.shared.b16 {%0,%1,%2,%3}, [%4];\n"
        : "=r"(r0), "=r"(r1), "=r"(r2), "=r"(r3) : "r"(addr));
}

__device__ __forceinline__ void ldsm_x4_trans(unsigned int addr,
    uint32_t& r0, uint32_t& r1, uint32_t& r2, uint32_t& r3) {
    asm volatile(
        "ldmatrix.sync.aligned.m8n8.x4.trans.shared.b16 {%0,%1,%2,%3}, [%4];\n"
        : "=r"(r0), "=r"(r1), "=r"(r2), "=r"(r3) : "r"(addr));
}

__device__ __forceinline__ uint32_t packh2(float lo, float hi) {
    __half2 h = __floats2half2_rn(lo, hi);
    return *(uint32_t*)&h;
}

// ---------------------------------------------------------------------------
// Elementwise f32 -> f16 conversion pass
// ---------------------------------------------------------------------------
__global__ void f32_to_f16_kernel(const float* __restrict__ src,
                                  __half* __restrict__ dst, int n4)
{
    int i = blockIdx.x * blockDim.x + threadIdx.x;
    if (i < n4) {
        float4 v = ((const float4*)src)[i];
        ((__half2*)dst)[2 * i]     = __floats2half2_rn(v.x, v.y);
        ((__half2*)dst)[2 * i + 1] = __floats2half2_rn(v.z, v.w);
    }
}

// ---------------------------------------------------------------------------
// In-place RoPE on Q (with 0.125 pre-scale) and K inside g_qkv.
// One thread per rotation pair. i decomposes as b|s|h|pair.
// ---------------------------------------------------------------------------
__global__ void rope_qk_kernel(__half* __restrict__ qkv,
                               const float* __restrict__ fcos,
                               const float* __restrict__ fsin)
{
    int i = blockIdx.x * blockDim.x + threadIdx.x;   // 0 .. B*S*E/2-1
    if (i >= Bq * Sq * Eq / 2) return;
    int pr = i & 31;
    int hh = (i >> 5) & 15;
    int s  = (i >> 9) & (Sq - 1);
    int bb = i >> 20;                                // Sq*Eq/2 = 2^20
    size_t off = ((size_t)(bb * Sq + s)) * (3 * Eq) + hh * Dq + 2 * pr;
    float c = fcos[s * 32 + pr], sn = fsin[s * 32 + pr];

    float2 q = __half22float2(*(__half2*)&qkv[off]);
    *(__half2*)&qkv[off] =
        __floats2half2_rn((q.x * c - q.y * sn) * 0.125f,
                          (q.x * sn + q.y * c) * 0.125f);

    float2 k = __half22float2(*(__half2*)&qkv[off + Eq]);
    *(__half2*)&qkv[off + Eq] =
        __floats2half2_rn(k.x * c - k.y * sn, k.x * sn + k.y * c);
}

// ---------------------------------------------------------------------------
// FP16 GEMM (f32 accum): 128x128x32 block, 256 threads = 8 warps,
// warp grid 2(M)x4(N), 64x32 warp tile. cp.async 3-stage. (R10/R11 proven)
// ---------------------------------------------------------------------------
#define GT_M 128
#define GT_N 128
#define GT_K 32
#define A_LDH 40
#define B_LDH 136
#define GA_SZ (GT_M * A_LDH)
#define GB_SZ (GT_K * B_LDH)
#define STAGE_SZ (GA_SZ + GB_SZ)
#define G_STAGES 3
#define GEMM_SMEM (G_STAGES * STAGE_SZ * sizeof(__half))   // 56832 B
#define C_STAGE_LD 20

template <typename OutT>
__global__ __launch_bounds__(256, 2) void gemm_f16(
    const __half* __restrict__ A, const __half* __restrict__ B,
    OutT* __restrict__ C, int M, int N, int K)
{
    extern __shared__ __half gsm[];

    const int tid = threadIdx.x;
    const int warp = tid >> 5;
    const int lane = tid & 31;
    const int wm = warp & 1;
    const int wn = warp >> 1;
    const int brow = blockIdx.y * GT_M;
    const int bcol = blockIdx.x * GT_N;

    const int arw = tid >> 2;
    const int ac8 = (tid & 3) * 8;
    const int brw = tid >> 4;
    const int bc8 = (tid & 15) * 8;

    wmma::fragment<wmma::accumulator, 16, 16, 16, float> c[4][2];
#pragma unroll
    for (int i = 0; i < 4; i++)
#pragma unroll
        for (int j = 0; j < 2; j++) wmma::fill_fragment(c[i][j], 0.f);

    const int T = K / GT_K;

    auto issue = [&](int t) {
        __half* dst = gsm + (t % G_STAGES) * STAGE_SZ;
        int k0 = t * GT_K;
#pragma unroll
        for (int p = 0; p < 2; p++)
            cp16(&dst[(arw + p * 64) * A_LDH + ac8],
                 &A[(size_t)(brow + arw + p * 64) * K + k0 + ac8]);
#pragma unroll
        for (int p = 0; p < 2; p++)
            cp16(&dst[GA_SZ + (brw + p * 16) * B_LDH + bc8],
                 &B[(size_t)(k0 + brw + p * 16) * N + bcol + bc8]);
        cp_commit();
    };

    issue(0);
    issue(1);

    for (int t = 0; t < T; t++) {
        cp_wait<G_STAGES - 2>();
        __syncthreads();

        if (t + G_STAGES - 1 < T) issue(t + G_STAGES - 1);

        __half* Ac = gsm + (t % G_STAGES) * STAGE_SZ;
        __half* Bc = Ac + GA_SZ;
#pragma unroll
        for (int kk = 0; kk < GT_K; kk += 16) {
            wmma::fragment<wmma::matrix_a, 16, 16, 16, __half, wmma::row_major> a[4];
            wmma::fragment<wmma::matrix_b, 16, 16, 16, __half, wmma::row_major> bf[2];
#pragma unroll
            for (int i = 0; i < 4; i++)
                wmma::load_matrix_sync(a[i], &Ac[(wm * 64 + i * 16) * A_LDH + kk], A_LDH);
#pragma unroll
            for (int j = 0; j < 2; j++)
                wmma::load_matrix_sync(bf[j], &Bc[kk * B_LDH + wn * 32 + j * 16], B_LDH);
#pragma unroll
            for (int i = 0; i < 4; i++)
#pragma unroll
                for (int j = 0; j < 2; j++)
                    wmma::mma_sync(c[i][j], a[i], bf[j], c[i][j]);
        }
        __syncthreads();
    }

    if constexpr (std::is_same<OutT, float>::value) {
#pragma unroll
        for (int i = 0; i < 4; i++)
#pragma unroll
            for (int j = 0; j < 2; j++)
                wmma::store_matrix_sync(
                    &C[(size_t)(brow + wm * 64 + i * 16) * N + bcol + wn * 32 + j * 16],
                    c[i][j], N, wmma::mem_row_major);
    } else {
        float* stage = (float*)gsm + warp * (16 * C_STAGE_LD);
        const int r = lane >> 1;
        const int c0 = (lane & 1) * 8;
#pragma unroll
        for (int i = 0; i < 4; i++)
#pragma unroll
            for (int j = 0; j < 2; j++) {
                wmma::store_matrix_sync(stage, c[i][j], C_STAGE_LD,
                                        wmma::mem_row_major);
                __syncwarp();
                const float* sp = stage + r * C_STAGE_LD + c0;
                __half2 h[4];
#pragma unroll
                for (int q = 0; q < 4; q++)
                    h[q] = __floats2half2_rn(sp[2 * q], sp[2 * q + 1]);
                *(uint4*)&C[(size_t)(brow + wm * 64 + i * 16 + r) * N +
                            bcol + wn * 32 + j * 16 + c0] = *(uint4*)h;
                __syncwarp();
            }
    }
}

// ---------------------------------------------------------------------------
// Register-resident flash attention, fp16 mma m16n8k16.
// R11 base; S-phase K loads now via ldmatrix.x4 (non-trans): one instruction
// delivers b-frags for two n-chunks at one k-chunk.
// ---------------------------------------------------------------------------
#define QLDH 72
#define KLDH 72
#define VLDH 72
#define KV_SZ (64 * KLDH)
#define FA_SMEM (4 * KV_SZ * sizeof(__half))   // 36864 B

__global__ __launch_bounds__(256, 2) void flash_attn_f16(
    const __half* __restrict__ qkv,
    __half* __restrict__ attn)
{
    extern __shared__ __half smh[];
    __half* Qstage = smh;

    const int tid  = threadIdx.x;
    const int lane = tid & 31;
    const int wr   = tid >> 5;
    const int g    = lane >> 2;
    const int j    = lane & 3;
    const int qi   = blockIdx.x;
    const int b    = blockIdx.y >> 4;
    const int h    = blockIdx.y & 15;
    const int qbase = qi * 128;
    const size_t rs3 = 3 * Eq;
    const size_t base = (size_t)b * Sq * rs3 + (size_t)h * Dq;

    for (int t = tid; t < 128 * 8; t += 256) {
        int r = t >> 3, c8 = (t & 7) * 8;
        *(uint4*)&Qstage[r * QLDH + c8] =
            *(const uint4*)&qkv[base + (size_t)(qbase + r) * rs3 + c8];
    }
    __syncthreads();

    uint32_t qa[4][4];
    {
        const int r0 = wr * 16 + g;
#pragma unroll
        for (int kc = 0; kc < 4; kc++) {
            int col = kc * 16 + 2 * j;
            qa[kc][0] = *(const uint32_t*)&Qstage[r0 * QLDH + col];
            qa[kc][1] = *(const uint32_t*)&Qstage[(r0 + 8) * QLDH + col];
            qa[kc][2] = *(const uint32_t*)&Qstage[r0 * QLDH + col + 8];
            qa[kc][3] = *(const uint32_t*)&Qstage[(r0 + 8) * QLDH + col + 8];
        }
    }
    __syncthreads();

    float od[8][4];
#pragma unroll
    for (int n = 0; n < 8; n++)
#pragma unroll
        for (int i = 0; i < 4; i++) od[n][i] = 0.f;

    float m0 = -1e30f, m1 = -1e30f, l0 = 0.f, l1 = 0.f;

    const int wq_lo = qbase + wr * 16;
    const int wq_hi = wq_lo + 15;
    const int r0g = wq_lo + g;
    const int r1g = r0g + 8;
    const int ntiles = 2 * qi + 2;

    // V ldmatrix.trans lane offsets
    const int lm_m  = lane >> 3;
    const int lm_rr = lane & 7;
    const int lm_keyoff = (lm_m & 1) * 8 + lm_rr;
    const int lm_dimoff = (lm_m >> 1) * 8;
    // K ldmatrix (non-trans) lane offsets: tile ti = lane>>3, row rr = lane&7
    // tile layout: t0=(nc_even,dimlo) t1=(nc_even,dimhi) t2=(nc_odd,dimlo) t3=(nc_odd,dimhi)
    const int kls_key = ((lane >> 4) & 1) * 8 + (lane & 7);  // (ti>>1)*8 + rr
    const int kls_dim = ((lane >> 3) & 1) * 8;               // (ti&1)*8

    auto issue_tile = [&](int kt) {
        __half* kd = smh + (kt & 1) * 2 * KV_SZ;
        __half* vd = kd + KV_SZ;
        const int kb = kt * 64;
#pragma unroll
        for (int p = 0; p < 2; p++) {
            int t = tid + p * 256;
            int r = t >> 3, c8 = (t & 7) * 8;
            cp16(&kd[r * KLDH + c8],
                 &qkv[base + Eq + (size_t)(kb + r) * rs3 + c8]);
        }
#pragma unroll
        for (int p = 0; p < 2; p++) {
            int t = tid + p * 256;
            int r = t >> 3, c8 = (t & 7) * 8;
            cp16(&vd[r * VLDH + c8],
                 &qkv[base + 2 * Eq + (size_t)(kb + r) * rs3 + c8]);
        }
        cp_commit();
    };

    issue_tile(0);

    for (int kt = 0; kt < ntiles; ++kt) {
        if (kt + 1 < ntiles) {
            issue_tile(kt + 1);
            cp_wait<1>();
        } else {
            cp_wait<0>();
        }
        __syncthreads();

        const __half* Ks = smh + (kt & 1) * 2 * KV_SZ;
        const __half* Vs = Ks + KV_SZ;
        const int kbase = kt * 64;

        if (kbase <= wq_hi) {
            // ---- S = Q @ K^T (K b-frags via ldmatrix.x4) ----
            float s[8][4];
#pragma unroll
            for (int nc2 = 0; nc2 < 4; nc2++) {
                float* se = s[2 * nc2];
                float* so = s[2 * nc2 + 1];
                se[0] = se[1] = se[2] = se[3] = 0.f;
                so[0] = so[1] = so[2] = so[3] = 0.f;
#pragma unroll
                for (int kc = 0; kc < 4; kc++) {
                    unsigned int addr = (unsigned int)__cvta_generic_to_shared(
                        &Ks[(nc2 * 16 + kls_key) * KLDH + kc * 16 + kls_dim]);
                    uint32_t b0, b1, b2, b3;
                    ldsm_x4(addr, b0, b1, b2, b3);
                    mma_f16(se, qa[kc], b0, b1);
                    mma_f16(so, qa[kc], b2, b3);
                }
            }

            // ---- causal mask ----
            if (kbase + 63 > wq_lo) {
#pragma unroll
                for (int nc = 0; nc < 8; nc++) {
                    int c0 = kbase + nc * 8 + 2 * j;
                    if (c0 > r0g)     s[nc][0] = -1e30f;
                    if (c0 + 1 > r0g) s[nc][1] = -1e30f;
                    if (c0 > r1g)     s[nc][2] = -1e30f;
                    if (c0 + 1 > r1g) s[nc][3] = -1e30f;
                }
            }

            // ---- online softmax ----
            float mx0 = -1e30f, mx1 = -1e30f;
#pragma unroll
            for (int nc = 0; nc < 8; nc++) {
                mx0 = fmaxf(mx0, fmaxf(s[nc][0], s[nc][1]));
                mx1 = fmaxf(mx1, fmaxf(s[nc][2], s[nc][3]));
            }
            mx0 = fmaxf(mx0, __shfl_xor_sync(0xffffffffu, mx0, 1));
            mx0 = fmaxf(mx0, __shfl_xor_sync(0xffffffffu, mx0, 2));
            mx1 = fmaxf(mx1, __shfl_xor_sync(0xffffffffu, mx1, 1));
            mx1 = fmaxf(mx1, __shfl_xor_sync(0xffffffffu, mx1, 2));

            float mn0 = fmaxf(m0, mx0);
            float mn1 = fmaxf(m1, mx1);
            float corr0 = __expf(m0 - mn0);
            float corr1 = __expf(m1 - mn1);
            m0 = mn0; m1 = mn1;

            float sum0 = 0.f, sum1 = 0.f;
#pragma unroll
            for (int nc = 0; nc < 8; nc++) {
                s[nc][0] = __expf(s[nc][0] - mn0);
                s[nc][1] = __expf(s[nc][1] - mn0);
                s[nc][2] = __expf(s[nc][2] - mn1);
                s[nc][3] = __expf(s[nc][3] - mn1);
                sum0 += s[nc][0] + s[nc][1];
                sum1 += s[nc][2] + s[nc][3];
            }
            sum0 += __shfl_xor_sync(0xffffffffu, sum0, 1);
            sum0 += __shfl_xor_sync(0xffffffffu, sum0, 2);
            sum1 += __shfl_xor_sync(0xffffffffu, sum1, 1);
            sum1 += __shfl_xor_sync(0xffffffffu, sum1, 2);
            l0 = l0 * corr0 + sum0;
            l1 = l1 * corr1 + sum1;

#pragma unroll
            for (int n = 0; n < 8; n++) {
                od[n][0] *= corr0; od[n][1] *= corr0;
                od[n][2] *= corr1; od[n][3] *= corr1;
            }

            // ---- P c-frags -> fp16 a-frags (layouts match) ----
            uint32_t pa[4][4];
#pragma unroll
            for (int kc = 0; kc < 4; kc++) {
                pa[kc][0] = packh2(s[2 * kc][0],     s[2 * kc][1]);
                pa[kc][1] = packh2(s[2 * kc][2],     s[2 * kc][3]);
                pa[kc][2] = packh2(s[2 * kc + 1][0], s[2 * kc + 1][1]);
                pa[kc][3] = packh2(s[2 * kc + 1][2], s[2 * kc + 1][3]);
            }

            // ---- O += P @ V (V b-frags via ldmatrix.x4.trans) ----
#pragma unroll
            for (int nd2 = 0; nd2 < 4; nd2++) {
#pragma unroll
                for (int kc = 0; kc < 4; kc++) {
                    unsigned int addr = (unsigned int)__cvta_generic_to_shared(
                        &Vs[(kc * 16 + lm_keyoff) * VLDH + nd2 * 16 + lm_dimoff]);
                    uint32_t b0, b1, b2, b3;
                    ldsm_x4_trans(addr, b0, b1, b2, b3);
                    mma_f16(od[2 * nd2],     pa[kc], b0, b1);
                    mma_f16(od[2 * nd2 + 1], pa[kc], b2, b3);
                }
            }
        }
        __syncthreads();
    }

    // ---- epilogue ----
    {
        float inv0 = 1.f / l0;
        float inv1 = 1.f / l1;
        __half* op0 = &attn[((size_t)b * Sq + r0g) * Eq + h * Dq];
        __half* op1 = &attn[((size_t)b * Sq + r1g) * Eq + h * Dq];
#pragma unroll
        for (int nd = 0; nd < 8; nd++) {
            int c0 = nd * 8 + 2 * j;
            *(__half2*)&op0[c0] = __floats2half2_rn(od[nd][0] * inv0, od[nd][1] * inv0);
            *(__half2*)&op1[c0] = __floats2half2_rn(od[nd][2] * inv1, od[nd][3] * inv1);
        }
    }
}

// ---------------------------------------------------------------------------
extern "C" void kernel_launch(void* const* d_in, const int* in_sizes, int n_in,
                              void* d_out, int out_size)
{
    const float* x     = (const float*)d_in[0];
    const float* w_qkv = (const float*)d_in[1];
    const float* w_out = (const float*)d_in[2];
    const float* fcos  = (const float*)d_in[3];
    const float* fsin  = (const float*)d_in[4];
    float* out = (float*)d_out;

    __half *qkv, *attn, *xh, *wqkvh, *wouth;
    cudaGetSymbolAddress((void**)&qkv, g_qkv);
    cudaGetSymbolAddress((void**)&attn, g_attn);
    cudaGetSymbolAddress((void**)&xh, g_xh);
    cudaGetSymbolAddress((void**)&wqkvh, g_wqkvh);
    cudaGetSymbolAddress((void**)&wouth, g_wouth);

    cudaFuncSetAttribute(gemm_f16<__half>,
                         cudaFuncAttributeMaxDynamicSharedMemorySize, GEMM_SMEM);
    cudaFuncSetAttribute(gemm_f16<float>,
                         cudaFuncAttributeMaxDynamicSharedMemorySize, GEMM_SMEM);
    cudaFuncSetAttribute(flash_attn_f16,
                         cudaFuncAttributeMaxDynamicSharedMemorySize, FA_SMEM);

    // 0) fp16 conversion of GEMM inputs
    {
        int n4x = Bq * Sq * Eq / 4;
        int n4q = Eq * 3 * Eq / 4;
        int n4o = Eq * Eq / 4;
        f32_to_f16_kernel<<<(n4x + 255) / 256, 256>>>(x, xh, n4x);
        f32_to_f16_kernel<<<(n4q + 255) / 256, 256>>>(w_qkv, wqkvh, n4q);
        f32_to_f16_kernel<<<(n4o + 255) / 256, 256>>>(w_out, wouth, n4o);
    }

    // 1) QKV projection -> fp16 qkv
    gemm_f16<__half><<<dim3(3 * Eq / GT_N, Bq * Sq / GT_M), 256, GEMM_SMEM>>>(
        xh, wqkvh, qkv, Bq * Sq, 3 * Eq, Eq);

    // 1b) in-place RoPE on Q (pre-scaled) and K
    {
        int n = Bq * Sq * Eq / 2;
        rope_qk_kernel<<<(n + 255) / 256, 256>>>(qkv, fcos, fsin);
    }

    // 2) causal flash attention (fp16 mma, double-buffered cp.async K/V)
    flash_attn_f16<<<dim3(Sq / 128, Bq * Hq), 256, FA_SMEM>>>(qkv, attn);

    // 3) output projection -> fp32 out
    gemm_f16<float><<<dim3(Eq / GT_N, Bq * Sq / GT_M), 256, GEMM_SMEM>>>(
        attn, wouth, out, Bq * Sq, Eq, Eq);
}

// round 15
// speedup vs baseline: 1.0810x; 1.0196x over previous
#include <cuda_runtime.h>
#include <cuda_bf16.h>
#include <cuda_fp16.h>
#include <mma.h>
#include <cstdint>
#include <type_traits>

using namespace nvcuda;

#define Bq 2
#define Sq 2048
#define Eq 1024
#define Hq 16
#define Dq 64

// Scratch buffers (no cudaMalloc allowed)
__device__ __half g_qkv[(size_t)Bq * Sq * 3 * Eq];    // [B*S, 3E] fp16 (RoPE'd)
__device__ __half g_attn[(size_t)Bq * Sq * Eq];       // [B*S, E] fp16
__device__ __half g_xh[(size_t)Bq * Sq * Eq];         // fp16 x
__device__ __half g_wqkvh[(size_t)Eq * 3 * Eq];       // fp16 w_qkv
__device__ __half g_wouth[(size_t)Eq * Eq];           // fp16 w_out

// ---------------------------------------------------------------------------
// helpers
// ---------------------------------------------------------------------------
__device__ __forceinline__ void cp16(void* dst_smem, const void* src) {
    unsigned int d = (unsigned int)__cvta_generic_to_shared(dst_smem);
    asm volatile("cp.async.cg.shared.global [%0], [%1], 16;\n" :: "r"(d), "l"(src));
}
__device__ __forceinline__ void cp_commit() {
    asm volatile("cp.async.commit_group;\n");
}
template <int N> __device__ __forceinline__ void cp_wait() {
    asm volatile("cp.async.wait_group %0;\n" :: "n"(N));
}

// mma m16n8k16 fp16 inputs, f32 accum
__device__ __forceinline__ void mma_f16(float* d, const uint32_t* a,
                                        uint32_t b0, uint32_t b1) {
    asm volatile(
        "mma.sync.aligned.m16n8k16.row.col.f32.f16.f16.f32 "
        "{%0,%1,%2,%3}, {%4,%5,%6,%7}, {%8,%9}, {%0,%1,%2,%3};\n"
        : "+f"(d[0]), "+f"(d[1]), "+f"(d[2]), "+f"(d[3])
        : "r"(a[0]), "r"(a[1]), "r"(a[2]), "r"(a[3]), "r"(b0), "r"(b1));
}

__device__ __forceinline__ void ldsm_x4(unsigned int addr,
    uint32_t& r0, uint32_t& r1, uint32_t& r2, uint32_t& r3) {
    asm volatile(
        "ldmatrix.sync.aligned.m8n8.x4.shared.b16 {%0,%1,%2,%3}, [%4];\n"
        : "=r"(r0), "=r"(r1), "=r"(r2), "=r"(r3) : "r"(addr));
}

__device__ __forceinline__ void ldsm_x4_trans(unsigned int addr,
    uint32_t& r0, uint32_t& r1, uint32_t& r2, uint32_t& r3) {
    asm volatile(
        "ldmatrix.sync.aligned.m8n8.x4.trans.shared.b16 {%0,%1,%2,%3}, [%4];\n"
        : "=r"(r0), "=r"(r1), "=r"(r2), "=r"(r3) : "r"(addr));
}

__device__ __forceinline__ uint32_t packh2(float lo, float hi) {
    __half2 h = __floats2half2_rn(lo, hi);
    return *(uint32_t*)&h;
}

// ---------------------------------------------------------------------------
// Merged elementwise f32 -> f16 conversion (x, w_qkv, w_out in one launch)
// ---------------------------------------------------------------------------
#define N4X (Bq * Sq * Eq / 4)
#define N4Q (Eq * 3 * Eq / 4)
#define N4O (Eq * Eq / 4)

__global__ void convert_all_kernel(const float* __restrict__ x,   __half* __restrict__ xh,
                                   const float* __restrict__ wq,  __half* __restrict__ wqh,
                                   const float* __restrict__ wo,  __half* __restrict__ woh)
{
    int i = blockIdx.x * blockDim.x + threadIdx.x;
    const float* src;
    __half* dst;
    int k;
    if (i < N4X)            { src = x;  dst = xh;  k = i; }
    else if (i < N4X + N4Q) { src = wq; dst = wqh; k = i - N4X; }
    else if (i < N4X + N4Q + N4O) { src = wo; dst = woh; k = i - N4X - N4Q; }
    else return;
    float4 v = ((const float4*)src)[k];
    ((__half2*)dst)[2 * k]     = __floats2half2_rn(v.x, v.y);
    ((__half2*)dst)[2 * k + 1] = __floats2half2_rn(v.z, v.w);
}

// ---------------------------------------------------------------------------
// In-place RoPE on Q (with 0.125 pre-scale) and K inside g_qkv.
// ---------------------------------------------------------------------------
__global__ void rope_qk_kernel(__half* __restrict__ qkv,
                               const float* __restrict__ fcos,
                               const float* __restrict__ fsin)
{
    int i = blockIdx.x * blockDim.x + threadIdx.x;   // 0 .. B*S*E/2-1
    if (i >= Bq * Sq * Eq / 2) return;
    int pr = i & 31;
    int hh = (i >> 5) & 15;
    int s  = (i >> 9) & (Sq - 1);
    int bb = i >> 20;
    size_t off = ((size_t)(bb * Sq + s)) * (3 * Eq) + hh * Dq + 2 * pr;
    float c = fcos[s * 32 + pr], sn = fsin[s * 32 + pr];

    float2 q = __half22float2(*(__half2*)&qkv[off]);
    *(__half2*)&qkv[off] =
        __floats2half2_rn((q.x * c - q.y * sn) * 0.125f,
                          (q.x * sn + q.y * c) * 0.125f);

    float2 k = __half22float2(*(__half2*)&qkv[off + Eq]);
    *(__half2*)&qkv[off + Eq] =
        __floats2half2_rn(k.x * c - k.y * sn, k.x * sn + k.y * c);
}

// ---------------------------------------------------------------------------
// FP16 GEMM (f32 accum): 128x128x32 block, 256 threads = 8 warps,
// warp grid 2(M)x4(N), 64x32 warp tile. cp.async 3-stage. (R10/R11 proven)
// ---------------------------------------------------------------------------
#define GT_M 128
#define GT_N 128
#define GT_K 32
#define A_LDH 40
#define B_LDH 136
#define GA_SZ (GT_M * A_LDH)
#define GB_SZ (GT_K * B_LDH)
#define STAGE_SZ (GA_SZ + GB_SZ)
#define G_STAGES 3
#define GEMM_SMEM (G_STAGES * STAGE_SZ * sizeof(__half))   // 56832 B
#define C_STAGE_LD 20

template <typename OutT>
__global__ __launch_bounds__(256, 2) void gemm_f16(
    const __half* __restrict__ A, const __half* __restrict__ B,
    OutT* __restrict__ C, int M, int N, int K)
{
    extern __shared__ __half gsm[];

    const int tid = threadIdx.x;
    const int warp = tid >> 5;
    const int lane = tid & 31;
    const int wm = warp & 1;
    const int wn = warp >> 1;
    const int brow = blockIdx.y * GT_M;
    const int bcol = blockIdx.x * GT_N;

    const int arw = tid >> 2;
    const int ac8 = (tid & 3) * 8;
    const int brw = tid >> 4;
    const int bc8 = (tid & 15) * 8;

    wmma::fragment<wmma::accumulator, 16, 16, 16, float> c[4][2];
#pragma unroll
    for (int i = 0; i < 4; i++)
#pragma unroll
        for (int j = 0; j < 2; j++) wmma::fill_fragment(c[i][j], 0.f);

    const int T = K / GT_K;

    auto issue = [&](int t) {
        __half* dst = gsm + (t % G_STAGES) * STAGE_SZ;
        int k0 = t * GT_K;
#pragma unroll
        for (int p = 0; p < 2; p++)
            cp16(&dst[(arw + p * 64) * A_LDH + ac8],
                 &A[(size_t)(brow + arw + p * 64) * K + k0 + ac8]);
#pragma unroll
        for (int p = 0; p < 2; p++)
            cp16(&dst[GA_SZ + (brw + p * 16) * B_LDH + bc8],
                 &B[(size_t)(k0 + brw + p * 16) * N + bcol + bc8]);
        cp_commit();
    };

    issue(0);
    issue(1);

    for (int t = 0; t < T; t++) {
        cp_wait<G_STAGES - 2>();
        __syncthreads();

        if (t + G_STAGES - 1 < T) issue(t + G_STAGES - 1);

        __half* Ac = gsm + (t % G_STAGES) * STAGE_SZ;
        __half* Bc = Ac + GA_SZ;
#pragma unroll
        for (int kk = 0; kk < GT_K; kk += 16) {
            wmma::fragment<wmma::matrix_a, 16, 16, 16, __half, wmma::row_major> a[4];
            wmma::fragment<wmma::matrix_b, 16, 16, 16, __half, wmma::row_major> bf[2];
#pragma unroll
            for (int i = 0; i < 4; i++)
                wmma::load_matrix_sync(a[i], &Ac[(wm * 64 + i * 16) * A_LDH + kk], A_LDH);
#pragma unroll
            for (int j = 0; j < 2; j++)
                wmma::load_matrix_sync(bf[j], &Bc[kk * B_LDH + wn * 32 + j * 16], B_LDH);
#pragma unroll
            for (int i = 0; i < 4; i++)
#pragma unroll
                for (int j = 0; j < 2; j++)
                    wmma::mma_sync(c[i][j], a[i], bf[j], c[i][j]);
        }
        __syncthreads();
    }

    if constexpr (std::is_same<OutT, float>::value) {
#pragma unroll
        for (int i = 0; i < 4; i++)
#pragma unroll
            for (int j = 0; j < 2; j++)
                wmma::store_matrix_sync(
                    &C[(size_t)(brow + wm * 64 + i * 16) * N + bcol + wn * 32 + j * 16],
                    c[i][j], N, wmma::mem_row_major);
    } else {
        float* stage = (float*)gsm + warp * (16 * C_STAGE_LD);
        const int r = lane >> 1;
        const int c0 = (lane & 1) * 8;
#pragma unroll
        for (int i = 0; i < 4; i++)
#pragma unroll
            for (int j = 0; j < 2; j++) {
                wmma::store_matrix_sync(stage, c[i][j], C_STAGE_LD,
                                        wmma::mem_row_major);
                __syncwarp();
                const float* sp = stage + r * C_STAGE_LD + c0;
                __half2 h[4];
#pragma unroll
                for (int q = 0; q < 4; q++)
                    h[q] = __floats2half2_rn(sp[2 * q], sp[2 * q + 1]);
                *(uint4*)&C[(size_t)(brow + wm * 64 + i * 16 + r) * N +
                            bcol + wn * 32 + j * 16 + c0] = *(uint4*)h;
                __syncwarp();
            }
    }
}

// ---------------------------------------------------------------------------
// Register-resident flash attention, fp16 mma m16n8k16.
// R14 base + reversed qi order (heavy causal CTAs scheduled first).
// ---------------------------------------------------------------------------
#define QLDH 72
#define KLDH 72
#define VLDH 72
#define KV_SZ (64 * KLDH)
#define FA_SMEM (4 * KV_SZ * sizeof(__half))   // 36864 B

__global__ __launch_bounds__(256, 2) void flash_attn_f16(
    const __half* __restrict__ qkv,
    __half* __restrict__ attn)
{
    extern __shared__ __half smh[];
    __half* Qstage = smh;

    const int tid  = threadIdx.x;
    const int lane = tid & 31;
    const int wr   = tid >> 5;
    const int g    = lane >> 2;
    const int j    = lane & 3;
    const int qi   = gridDim.x - 1 - blockIdx.x;   // heavy tiles first
    const int b    = blockIdx.y >> 4;
    const int h    = blockIdx.y & 15;
    const int qbase = qi * 128;
    const size_t rs3 = 3 * Eq;
    const size_t base = (size_t)b * Sq * rs3 + (size_t)h * Dq;

    for (int t = tid; t < 128 * 8; t += 256) {
        int r = t >> 3, c8 = (t & 7) * 8;
        *(uint4*)&Qstage[r * QLDH + c8] =
            *(const uint4*)&qkv[base + (size_t)(qbase + r) * rs3 + c8];
    }
    __syncthreads();

    uint32_t qa[4][4];
    {
        const int r0 = wr * 16 + g;
#pragma unroll
        for (int kc = 0; kc < 4; kc++) {
            int col = kc * 16 + 2 * j;
            qa[kc][0] = *(const uint32_t*)&Qstage[r0 * QLDH + col];
            qa[kc][1] = *(const uint32_t*)&Qstage[(r0 + 8) * QLDH + col];
            qa[kc][2] = *(const uint32_t*)&Qstage[r0 * QLDH + col + 8];
            qa[kc][3] = *(const uint32_t*)&Qstage[(r0 + 8) * QLDH + col + 8];
        }
    }
    __syncthreads();

    float od[8][4];
#pragma unroll
    for (int n = 0; n < 8; n++)
#pragma unroll
        for (int i = 0; i < 4; i++) od[n][i] = 0.f;

    float m0 = -1e30f, m1 = -1e30f, l0 = 0.f, l1 = 0.f;

    const int wq_lo = qbase + wr * 16;
    const int wq_hi = wq_lo + 15;
    const int r0g = wq_lo + g;
    const int r1g = r0g + 8;
    const int ntiles = 2 * qi + 2;

    // V ldmatrix.trans lane offsets
    const int lm_m  = lane >> 3;
    const int lm_rr = lane & 7;
    const int lm_keyoff = (lm_m & 1) * 8 + lm_rr;
    const int lm_dimoff = (lm_m >> 1) * 8;
    // K ldmatrix (non-trans) lane offsets
    const int kls_key = ((lane >> 4) & 1) * 8 + (lane & 7);
    const int kls_dim = ((lane >> 3) & 1) * 8;

    auto issue_tile = [&](int kt) {
        __half* kd = smh + (kt & 1) * 2 * KV_SZ;
        __half* vd = kd + KV_SZ;
        const int kb = kt * 64;
#pragma unroll
        for (int p = 0; p < 2; p++) {
            int t = tid + p * 256;
            int r = t >> 3, c8 = (t & 7) * 8;
            cp16(&kd[r * KLDH + c8],
                 &qkv[base + Eq + (size_t)(kb + r) * rs3 + c8]);
        }
#pragma unroll
        for (int p = 0; p < 2; p++) {
            int t = tid + p * 256;
            int r = t >> 3, c8 = (t & 7) * 8;
            cp16(&vd[r * VLDH + c8],
                 &qkv[base + 2 * Eq + (size_t)(kb + r) * rs3 + c8]);
        }
        cp_commit();
    };

    issue_tile(0);

    for (int kt = 0; kt < ntiles; ++kt) {
        if (kt + 1 < ntiles) {
            issue_tile(kt + 1);
            cp_wait<1>();
        } else {
            cp_wait<0>();
        }
        __syncthreads();

        const __half* Ks = smh + (kt & 1) * 2 * KV_SZ;
        const __half* Vs = Ks + KV_SZ;
        const int kbase = kt * 64;

        if (kbase <= wq_hi) {
            // ---- S = Q @ K^T (K b-frags via ldmatrix.x4) ----
            float s[8][4];
#pragma unroll
            for (int nc2 = 0; nc2 < 4; nc2++) {
                float* se = s[2 * nc2];
                float* so = s[2 * nc2 + 1];
                se[0] = se[1] = se[2] = se[3] = 0.f;
                so[0] = so[1] = so[2] = so[3] = 0.f;
#pragma unroll
                for (int kc = 0; kc < 4; kc++) {
                    unsigned int addr = (unsigned int)__cvta_generic_to_shared(
                        &Ks[(nc2 * 16 + kls_key) * KLDH + kc * 16 + kls_dim]);
                    uint32_t b0, b1, b2, b3;
                    ldsm_x4(addr, b0, b1, b2, b3);
                    mma_f16(se, qa[kc], b0, b1);
                    mma_f16(so, qa[kc], b2, b3);
                }
            }

            // ---- causal mask ----
            if (kbase + 63 > wq_lo) {
#pragma unroll
                for (int nc = 0; nc < 8; nc++) {
                    int c0 = kbase + nc * 8 + 2 * j;
                    if (c0 > r0g)     s[nc][0] = -1e30f;
                    if (c0 + 1 > r0g) s[nc][1] = -1e30f;
                    if (c0 > r1g)     s[nc][2] = -1e30f;
                    if (c0 + 1 > r1g) s[nc][3] = -1e30f;
                }
            }

            // ---- online softmax ----
            float mx0 = -1e30f, mx1 = -1e30f;
#pragma unroll
            for (int nc = 0; nc < 8; nc++) {
                mx0 = fmaxf(mx0, fmaxf(s[nc][0], s[nc][1]));
                mx1 = fmaxf(mx1, fmaxf(s[nc][2], s[nc][3]));
            }
            mx0 = fmaxf(mx0, __shfl_xor_sync(0xffffffffu, mx0, 1));
            mx0 = fmaxf(mx0, __shfl_xor_sync(0xffffffffu, mx0, 2));
            mx1 = fmaxf(mx1, __shfl_xor_sync(0xffffffffu, mx1, 1));
            mx1 = fmaxf(mx1, __shfl_xor_sync(0xffffffffu, mx1, 2));

            float mn0 = fmaxf(m0, mx0);
            float mn1 = fmaxf(m1, mx1);
            float corr0 = __expf(m0 - mn0);
            float corr1 = __expf(m1 - mn1);
            m0 = mn0; m1 = mn1;

            float sum0 = 0.f, sum1 = 0.f;
#pragma unroll
            for (int nc = 0; nc < 8; nc++) {
                s[nc][0] = __expf(s[nc][0] - mn0);
                s[nc][1] = __expf(s[nc][1] - mn0);
                s[nc][2] = __expf(s[nc][2] - mn1);
                s[nc][3] = __expf(s[nc][3] - mn1);
                sum0 += s[nc][0] + s[nc][1];
                sum1 += s[nc][2] + s[nc][3];
            }
            sum0 += __shfl_xor_sync(0xffffffffu, sum0, 1);
            sum0 += __shfl_xor_sync(0xffffffffu, sum0, 2);
            sum1 += __shfl_xor_sync(0xffffffffu, sum1, 1);
            sum1 += __shfl_xor_sync(0xffffffffu, sum1, 2);
            l0 = l0 * corr0 + sum0;
            l1 = l1 * corr1 + sum1;

#pragma unroll
            for (int n = 0; n < 8; n++) {
                od[n][0] *= corr0; od[n][1] *= corr0;
                od[n][2] *= corr1; od[n][3] *= corr1;
            }

            // ---- P c-frags -> fp16 a-frags (layouts match) ----
            uint32_t pa[4][4];
#pragma unroll
            for (int kc = 0; kc < 4; kc++) {
                pa[kc][0] = packh2(s[2 * kc][0],     s[2 * kc][1]);
                pa[kc][1] = packh2(s[2 * kc][2],     s[2 * kc][3]);
                pa[kc][2] = packh2(s[2 * kc + 1][0], s[2 * kc + 1][1]);
                pa[kc][3] = packh2(s[2 * kc + 1][2], s[2 * kc + 1][3]);
            }

            // ---- O += P @ V (V b-frags via ldmatrix.x4.trans) ----
#pragma unroll
            for (int nd2 = 0; nd2 < 4; nd2++) {
#pragma unroll
                for (int kc = 0; kc < 4; kc++) {
                    unsigned int addr = (unsigned int)__cvta_generic_to_shared(
                        &Vs[(kc * 16 + lm_keyoff) * VLDH + nd2 * 16 + lm_dimoff]);
                    uint32_t b0, b1, b2, b3;
                    ldsm_x4_trans(addr, b0, b1, b2, b3);
                    mma_f16(od[2 * nd2],     pa[kc], b0, b1);
                    mma_f16(od[2 * nd2 + 1], pa[kc], b2, b3);
                }
            }
        }
        __syncthreads();
    }

    // ---- epilogue ----
    {
        float inv0 = 1.f / l0;
        float inv1 = 1.f / l1;
        __half* op0 = &attn[((size_t)b * Sq + r0g) * Eq + h * Dq];
        __half* op1 = &attn[((size_t)b * Sq + r1g) * Eq + h * Dq];
#pragma unroll
        for (int nd = 0; nd < 8; nd++) {
            int c0 = nd * 8 + 2 * j;
            *(__half2*)&op0[c0] = __floats2half2_rn(od[nd][0] * inv0, od[nd][1] * inv0);
            *(__half2*)&op1[c0] = __floats2half2_rn(od[nd][2] * inv1, od[nd][3] * inv1);
        }
    }
}

// ---------------------------------------------------------------------------
extern "C" void kernel_launch(void* const* d_in, const int* in_sizes, int n_in,
                              void* d_out, int out_size)
{
    const float* x     = (const float*)d_in[0];
    const float* w_qkv = (const float*)d_in[1];
    const float* w_out = (const float*)d_in[2];
    const float* fcos  = (const float*)d_in[3];
    const float* fsin  = (const float*)d_in[4];
    float* out = (float*)d_out;

    __half *qkv, *attn, *xh, *wqkvh, *wouth;
    cudaGetSymbolAddress((void**)&qkv, g_qkv);
    cudaGetSymbolAddress((void**)&attn, g_attn);
    cudaGetSymbolAddress((void**)&xh, g_xh);
    cudaGetSymbolAddress((void**)&wqkvh, g_wqkvh);
    cudaGetSymbolAddress((void**)&wouth, g_wouth);

    cudaFuncSetAttribute(gemm_f16<__half>,
                         cudaFuncAttributeMaxDynamicSharedMemorySize, GEMM_SMEM);
    cudaFuncSetAttribute(gemm_f16<float>,
                         cudaFuncAttributeMaxDynamicSharedMemorySize, GEMM_SMEM);
    cudaFuncSetAttribute(flash_attn_f16,
                         cudaFuncAttributeMaxDynamicSharedMemorySize, FA_SMEM);

    // 0) merged fp16 conversion of all GEMM inputs (one launch)
    {
        int n4 = N4X + N4Q + N4O;
        convert_all_kernel<<<(n4 + 255) / 256, 256>>>(x, xh, w_qkv, wqkvh,
                                                      w_out, wouth);
    }

    // 1) QKV projection -> fp16 qkv
    gemm_f16<__half><<<dim3(3 * Eq / GT_N, Bq * Sq / GT_M), 256, GEMM_SMEM>>>(
        xh, wqkvh, qkv, Bq * Sq, 3 * Eq, Eq);

    // 1b) in-place RoPE on Q (pre-scaled) and K
    {
        int n = Bq * Sq * Eq / 2;
        rope_qk_kernel<<<(n + 255) / 256, 256>>>(qkv, fcos, fsin);
    }

    // 2) causal flash attention (fp16 mma, heavy-first scheduling)
    flash_attn_f16<<<dim3(Sq / 128, Bq * Hq), 256, FA_SMEM>>>(qkv, attn);

    // 3) output projection -> fp32 out
    gemm_f16<float><<<dim3(Eq / GT_N, Bq * Sq / GT_M), 256, GEMM_SMEM>>>(
        attn, wouth, out, Bq * Sq, Eq, Eq);
}

// round 16
// speedup vs baseline: 1.0921x; 1.0102x over previous
#include <cuda_runtime.h>
#include <cuda_bf16.h>
#include <cuda_fp16.h>
#include <mma.h>
#include <cstdint>
#include <type_traits>

using namespace nvcuda;

#define Bq 2
#define Sq 2048
#define Eq 1024
#define Hq 16
#define Dq 64

// Scratch buffers (no cudaMalloc allowed)
__device__ __half g_qkv[(size_t)Bq * Sq * 3 * Eq];    // [B*S, 3E] fp16 (RoPE'd)
__device__ __half g_attn[(size_t)Bq * Sq * Eq];       // [B*S, E] fp16
__device__ __half g_xh[(size_t)Bq * Sq * Eq];         // fp16 x
__device__ __half g_wqkvh[(size_t)Eq * 3 * Eq];       // fp16 w_qkv
__device__ __half g_wouth[(size_t)Eq * Eq];           // fp16 w_out

// ---------------------------------------------------------------------------
// helpers
// ---------------------------------------------------------------------------
__device__ __forceinline__ void cp16(void* dst_smem, const void* src) {
    unsigned int d = (unsigned int)__cvta_generic_to_shared(dst_smem);
    asm volatile("cp.async.cg.shared.global [%0], [%1], 16;\n" :: "r"(d), "l"(src));
}
__device__ __forceinline__ void cp_commit() {
    asm volatile("cp.async.commit_group;\n");
}
template <int N> __device__ __forceinline__ void cp_wait() {
    asm volatile("cp.async.wait_group %0;\n" :: "n"(N));
}

// mma m16n8k16 fp16 inputs, f32 accum
__device__ __forceinline__ void mma_f16(float* d, const uint32_t* a,
                                        uint32_t b0, uint32_t b1) {
    asm volatile(
        "mma.sync.aligned.m16n8k16.row.col.f32.f16.f16.f32 "
        "{%0,%1,%2,%3}, {%4,%5,%6,%7}, {%8,%9}, {%0,%1,%2,%3};\n"
        : "+f"(d[0]), "+f"(d[1]), "+f"(d[2]), "+f"(d[3])
        : "r"(a[0]), "r"(a[1]), "r"(a[2]), "r"(a[3]), "r"(b0), "r"(b1));
}

__device__ __forceinline__ void ldsm_x4(unsigned int addr,
    uint32_t& r0, uint32_t& r1, uint32_t& r2, uint32_t& r3) {
    asm volatile(
        "ldmatrix.sync.aligned.m8n8.x4.shared.b16 {%0,%1,%2,%3}, [%4];\n"
        : "=r"(r0), "=r"(r1), "=r"(r2), "=r"(r3) : "r"(addr));
}

__device__ __forceinline__ void ldsm_x4_trans(unsigned int addr,
    uint32_t& r0, uint32_t& r1, uint32_t& r2, uint32_t& r3) {
    asm volatile(
        "ldmatrix.sync.aligned.m8n8.x4.trans.shared.b16 {%0,%1,%2,%3}, [%4];\n"
        : "=r"(r0), "=r"(r1), "=r"(r2), "=r"(r3) : "r"(addr));
}

__device__ __forceinline__ uint32_t packh2(float lo, float hi) {
    __half2 h = __floats2half2_rn(lo, hi);
    return *(uint32_t*)&h;
}

// ---------------------------------------------------------------------------
// Merged elementwise f32 -> f16 conversion (x, w_qkv, w_out in one launch)
// ---------------------------------------------------------------------------
#define N4X (Bq * Sq * Eq / 4)
#define N4Q (Eq * 3 * Eq / 4)
#define N4O (Eq * Eq / 4)

__global__ void convert_all_kernel(const float* __restrict__ x,   __half* __restrict__ xh,
                                   const float* __restrict__ wq,  __half* __restrict__ wqh,
                                   const float* __restrict__ wo,  __half* __restrict__ woh)
{
    int i = blockIdx.x * blockDim.x + threadIdx.x;
    const float* src;
    __half* dst;
    int k;
    if (i < N4X)            { src = x;  dst = xh;  k = i; }
    else if (i < N4X + N4Q) { src = wq; dst = wqh; k = i - N4X; }
    else if (i < N4X + N4Q + N4O) { src = wo; dst = woh; k = i - N4X - N4Q; }
    else return;
    float4 v = ((const float4*)src)[k];
    ((__half2*)dst)[2 * k]     = __floats2half2_rn(v.x, v.y);
    ((__half2*)dst)[2 * k + 1] = __floats2half2_rn(v.z, v.w);
}

// ---------------------------------------------------------------------------
// In-place RoPE on Q (with 0.125*log2(e) pre-scale for exp2 softmax)
// and K inside g_qkv. One thread per rotation pair.
// ---------------------------------------------------------------------------
#define QSCALE (0.125f * 1.44269504088896340736f)

__global__ void rope_qk_kernel(__half* __restrict__ qkv,
                               const float* __restrict__ fcos,
                               const float* __restrict__ fsin)
{
    int i = blockIdx.x * blockDim.x + threadIdx.x;   // 0 .. B*S*E/2-1
    if (i >= Bq * Sq * Eq / 2) return;
    int pr = i & 31;
    int hh = (i >> 5) & 15;
    int s  = (i >> 9) & (Sq - 1);
    int bb = i >> 20;
    size_t off = ((size_t)(bb * Sq + s)) * (3 * Eq) + hh * Dq + 2 * pr;
    float c = fcos[s * 32 + pr], sn = fsin[s * 32 + pr];

    float2 q = __half22float2(*(__half2*)&qkv[off]);
    *(__half2*)&qkv[off] =
        __floats2half2_rn((q.x * c - q.y * sn) * QSCALE,
                          (q.x * sn + q.y * c) * QSCALE);

    float2 k = __half22float2(*(__half2*)&qkv[off + Eq]);
    *(__half2*)&qkv[off + Eq] =
        __floats2half2_rn(k.x * c - k.y * sn, k.x * sn + k.y * c);
}

// ---------------------------------------------------------------------------
// FP16 GEMM (f32 accum): 128x128x32 block, 256 threads = 8 warps,
// warp grid 2(M)x4(N), 64x32 warp tile. cp.async 3-stage. (R10/R11 proven)
// ---------------------------------------------------------------------------
#define GT_M 128
#define GT_N 128
#define GT_K 32
#define A_LDH 40
#define B_LDH 136
#define GA_SZ (GT_M * A_LDH)
#define GB_SZ (GT_K * B_LDH)
#define STAGE_SZ (GA_SZ + GB_SZ)
#define G_STAGES 3
#define GEMM_SMEM (G_STAGES * STAGE_SZ * sizeof(__half))   // 56832 B
#define C_STAGE_LD 20

template <typename OutT>
__global__ __launch_bounds__(256, 2) void gemm_f16(
    const __half* __restrict__ A, const __half* __restrict__ B,
    OutT* __restrict__ C, int M, int N, int K)
{
    extern __shared__ __half gsm[];

    const int tid = threadIdx.x;
    const int warp = tid >> 5;
    const int lane = tid & 31;
    const int wm = warp & 1;
    const int wn = warp >> 1;
    const int brow = blockIdx.y * GT_M;
    const int bcol = blockIdx.x * GT_N;

    const int arw = tid >> 2;
    const int ac8 = (tid & 3) * 8;
    const int brw = tid >> 4;
    const int bc8 = (tid & 15) * 8;

    wmma::fragment<wmma::accumulator, 16, 16, 16, float> c[4][2];
#pragma unroll
    for (int i = 0; i < 4; i++)
#pragma unroll
        for (int j = 0; j < 2; j++) wmma::fill_fragment(c[i][j], 0.f);

    const int T = K / GT_K;

    auto issue = [&](int t) {
        __half* dst = gsm + (t % G_STAGES) * STAGE_SZ;
        int k0 = t * GT_K;
#pragma unroll
        for (int p = 0; p < 2; p++)
            cp16(&dst[(arw + p * 64) * A_LDH + ac8],
                 &A[(size_t)(brow + arw + p * 64) * K + k0 + ac8]);
#pragma unroll
        for (int p = 0; p < 2; p++)
            cp16(&dst[GA_SZ + (brw + p * 16) * B_LDH + bc8],
                 &B[(size_t)(k0 + brw + p * 16) * N + bcol + bc8]);
        cp_commit();
    };

    issue(0);
    issue(1);

    for (int t = 0; t < T; t++) {
        cp_wait<G_STAGES - 2>();
        __syncthreads();

        if (t + G_STAGES - 1 < T) issue(t + G_STAGES - 1);

        __half* Ac = gsm + (t % G_STAGES) * STAGE_SZ;
        __half* Bc = Ac + GA_SZ;
#pragma unroll
        for (int kk = 0; kk < GT_K; kk += 16) {
            wmma::fragment<wmma::matrix_a, 16, 16, 16, __half, wmma::row_major> a[4];
            wmma::fragment<wmma::matrix_b, 16, 16, 16, __half, wmma::row_major> bf[2];
#pragma unroll
            for (int i = 0; i < 4; i++)
                wmma::load_matrix_sync(a[i], &Ac[(wm * 64 + i * 16) * A_LDH + kk], A_LDH);
#pragma unroll
            for (int j = 0; j < 2; j++)
                wmma::load_matrix_sync(bf[j], &Bc[kk * B_LDH + wn * 32 + j * 16], B_LDH);
#pragma unroll
            for (int i = 0; i < 4; i++)
#pragma unroll
                for (int j = 0; j < 2; j++)
                    wmma::mma_sync(c[i][j], a[i], bf[j], c[i][j]);
        }
        __syncthreads();
    }

    if constexpr (std::is_same<OutT, float>::value) {
#pragma unroll
        for (int i = 0; i < 4; i++)
#pragma unroll
            for (int j = 0; j < 2; j++)
                wmma::store_matrix_sync(
                    &C[(size_t)(brow + wm * 64 + i * 16) * N + bcol + wn * 32 + j * 16],
                    c[i][j], N, wmma::mem_row_major);
    } else {
        float* stage = (float*)gsm + warp * (16 * C_STAGE_LD);
        const int r = lane >> 1;
        const int c0 = (lane & 1) * 8;
#pragma unroll
        for (int i = 0; i < 4; i++)
#pragma unroll
            for (int j = 0; j < 2; j++) {
                wmma::store_matrix_sync(stage, c[i][j], C_STAGE_LD,
                                        wmma::mem_row_major);
                __syncwarp();
                const float* sp = stage + r * C_STAGE_LD + c0;
                __half2 h[4];
#pragma unroll
                for (int q = 0; q < 4; q++)
                    h[q] = __floats2half2_rn(sp[2 * q], sp[2 * q + 1]);
                *(uint4*)&C[(size_t)(brow + wm * 64 + i * 16 + r) * N +
                            bcol + wn * 32 + j * 16 + c0] = *(uint4*)h;
                __syncwarp();
            }
    }
}

// ---------------------------------------------------------------------------
// Register-resident flash attention, fp16 mma m16n8k16.
// exp2-domain softmax (log2e folded into Q scale); sum reduction deferred
// past the PV mma loop so shuffles overlap tensor issue.
// ---------------------------------------------------------------------------
#define QLDH 72
#define KLDH 72
#define VLDH 72
#define KV_SZ (64 * KLDH)
#define FA_SMEM (4 * KV_SZ * sizeof(__half))   // 36864 B

__global__ __launch_bounds__(256, 2) void flash_attn_f16(
    const __half* __restrict__ qkv,
    __half* __restrict__ attn)
{
    extern __shared__ __half smh[];
    __half* Qstage = smh;

    const int tid  = threadIdx.x;
    const int lane = tid & 31;
    const int wr   = tid >> 5;
    const int g    = lane >> 2;
    const int j    = lane & 3;
    const int qi   = gridDim.x - 1 - blockIdx.x;   // heavy tiles first
    const int b    = blockIdx.y >> 4;
    const int h    = blockIdx.y & 15;
    const int qbase = qi * 128;
    const size_t rs3 = 3 * Eq;
    const size_t base = (size_t)b * Sq * rs3 + (size_t)h * Dq;

    for (int t = tid; t < 128 * 8; t += 256) {
        int r = t >> 3, c8 = (t & 7) * 8;
        *(uint4*)&Qstage[r * QLDH + c8] =
            *(const uint4*)&qkv[base + (size_t)(qbase + r) * rs3 + c8];
    }
    __syncthreads();

    uint32_t qa[4][4];
    {
        const int r0 = wr * 16 + g;
#pragma unroll
        for (int kc = 0; kc < 4; kc++) {
            int col = kc * 16 + 2 * j;
            qa[kc][0] = *(const uint32_t*)&Qstage[r0 * QLDH + col];
            qa[kc][1] = *(const uint32_t*)&Qstage[(r0 + 8) * QLDH + col];
            qa[kc][2] = *(const uint32_t*)&Qstage[r0 * QLDH + col + 8];
            qa[kc][3] = *(const uint32_t*)&Qstage[(r0 + 8) * QLDH + col + 8];
        }
    }
    __syncthreads();

    float od[8][4];
#pragma unroll
    for (int n = 0; n < 8; n++)
#pragma unroll
        for (int i = 0; i < 4; i++) od[n][i] = 0.f;

    float m0 = -1e30f, m1 = -1e30f, l0 = 0.f, l1 = 0.f;

    const int wq_lo = qbase + wr * 16;
    const int wq_hi = wq_lo + 15;
    const int r0g = wq_lo + g;
    const int r1g = r0g + 8;
    const int ntiles = 2 * qi + 2;

    // V ldmatrix.trans lane offsets
    const int lm_m  = lane >> 3;
    const int lm_rr = lane & 7;
    const int lm_keyoff = (lm_m & 1) * 8 + lm_rr;
    const int lm_dimoff = (lm_m >> 1) * 8;
    // K ldmatrix (non-trans) lane offsets
    const int kls_key = ((lane >> 4) & 1) * 8 + (lane & 7);
    const int kls_dim = ((lane >> 3) & 1) * 8;

    auto issue_tile = [&](int kt) {
        __half* kd = smh + (kt & 1) * 2 * KV_SZ;
        __half* vd = kd + KV_SZ;
        const int kb = kt * 64;
#pragma unroll
        for (int p = 0; p < 2; p++) {
            int t = tid + p * 256;
            int r = t >> 3, c8 = (t & 7) * 8;
            cp16(&kd[r * KLDH + c8],
                 &qkv[base + Eq + (size_t)(kb + r) * rs3 + c8]);
        }
#pragma unroll
        for (int p = 0; p < 2; p++) {
            int t = tid + p * 256;
            int r = t >> 3, c8 = (t & 7) * 8;
            cp16(&vd[r * VLDH + c8],
                 &qkv[base + 2 * Eq + (size_t)(kb + r) * rs3 + c8]);
        }
        cp_commit();
    };

    issue_tile(0);

    for (int kt = 0; kt < ntiles; ++kt) {
        if (kt + 1 < ntiles) {
            issue_tile(kt + 1);
            cp_wait<1>();
        } else {
            cp_wait<0>();
        }
        __syncthreads();

        const __half* Ks = smh + (kt & 1) * 2 * KV_SZ;
        const __half* Vs = Ks + KV_SZ;
        const int kbase = kt * 64;

        if (kbase <= wq_hi) {
            // ---- S = Q @ K^T (K b-frags via ldmatrix.x4); scores in log2 domain ----
            float s[8][4];
#pragma unroll
            for (int nc2 = 0; nc2 < 4; nc2++) {
                float* se = s[2 * nc2];
                float* so = s[2 * nc2 + 1];
                se[0] = se[1] = se[2] = se[3] = 0.f;
                so[0] = so[1] = so[2] = so[3] = 0.f;
#pragma unroll
                for (int kc = 0; kc < 4; kc++) {
                    unsigned int addr = (unsigned int)__cvta_generic_to_shared(
                        &Ks[(nc2 * 16 + kls_key) * KLDH + kc * 16 + kls_dim]);
                    uint32_t b0, b1, b2, b3;
                    ldsm_x4(addr, b0, b1, b2, b3);
                    mma_f16(se, qa[kc], b0, b1);
                    mma_f16(so, qa[kc], b2, b3);
                }
            }

            // ---- causal mask ----
            if (kbase + 63 > wq_lo) {
#pragma unroll
                for (int nc = 0; nc < 8; nc++) {
                    int c0 = kbase + nc * 8 + 2 * j;
                    if (c0 > r0g)     s[nc][0] = -1e30f;
                    if (c0 + 1 > r0g) s[nc][1] = -1e30f;
                    if (c0 > r1g)     s[nc][2] = -1e30f;
                    if (c0 + 1 > r1g) s[nc][3] = -1e30f;
                }
            }

            // ---- online softmax (base-2) ----
            float mx0 = -1e30f, mx1 = -1e30f;
#pragma unroll
            for (int nc = 0; nc < 8; nc++) {
                mx0 = fmaxf(mx0, fmaxf(s[nc][0], s[nc][1]));
                mx1 = fmaxf(mx1, fmaxf(s[nc][2], s[nc][3]));
            }
            mx0 = fmaxf(mx0, __shfl_xor_sync(0xffffffffu, mx0, 1));
            mx0 = fmaxf(mx0, __shfl_xor_sync(0xffffffffu, mx0, 2));
            mx1 = fmaxf(mx1, __shfl_xor_sync(0xffffffffu, mx1, 1));
            mx1 = fmaxf(mx1, __shfl_xor_sync(0xffffffffu, mx1, 2));

            float mn0 = fmaxf(m0, mx0);
            float mn1 = fmaxf(m1, mx1);
            float corr0 = exp2f(m0 - mn0);
            float corr1 = exp2f(m1 - mn1);
            m0 = mn0; m1 = mn1;

            float sum0 = 0.f, sum1 = 0.f;
#pragma unroll
            for (int nc = 0; nc < 8; nc++) {
                s[nc][0] = exp2f(s[nc][0] - mn0);
                s[nc][1] = exp2f(s[nc][1] - mn0);
                s[nc][2] = exp2f(s[nc][2] - mn1);
                s[nc][3] = exp2f(s[nc][3] - mn1);
                sum0 += s[nc][0] + s[nc][1];
                sum1 += s[nc][2] + s[nc][3];
            }

            // rescale O accumulators (must precede PV accumulation)
#pragma unroll
            for (int n = 0; n < 8; n++) {
                od[n][0] *= corr0; od[n][1] *= corr0;
                od[n][2] *= corr1; od[n][3] *= corr1;
            }

            // ---- P c-frags -> fp16 a-frags (layouts match) ----
            uint32_t pa[4][4];
#pragma unroll
            for (int kc = 0; kc < 4; kc++) {
                pa[kc][0] = packh2(s[2 * kc][0],     s[2 * kc][1]);
                pa[kc][1] = packh2(s[2 * kc][2],     s[2 * kc][3]);
                pa[kc][2] = packh2(s[2 * kc + 1][0], s[2 * kc + 1][1]);
                pa[kc][3] = packh2(s[2 * kc + 1][2], s[2 * kc + 1][3]);
            }

            // ---- O += P @ V (V b-frags via ldmatrix.x4.trans) ----
#pragma unroll
            for (int nd2 = 0; nd2 < 4; nd2++) {
#pragma unroll
                for (int kc = 0; kc < 4; kc++) {
                    unsigned int addr = (unsigned int)__cvta_generic_to_shared(
                        &Vs[(kc * 16 + lm_keyoff) * VLDH + nd2 * 16 + lm_dimoff]);
                    uint32_t b0, b1, b2, b3;
                    ldsm_x4_trans(addr, b0, b1, b2, b3);
                    mma_f16(od[2 * nd2],     pa[kc], b0, b1);
                    mma_f16(od[2 * nd2 + 1], pa[kc], b2, b3);
                }
            }

            // ---- deferred sum reduction (overlaps with PV issue above) ----
            sum0 += __shfl_xor_sync(0xffffffffu, sum0, 1);
            sum0 += __shfl_xor_sync(0xffffffffu, sum0, 2);
            sum1 += __shfl_xor_sync(0xffffffffu, sum1, 1);
            sum1 += __shfl_xor_sync(0xffffffffu, sum1, 2);
            l0 = l0 * corr0 + sum0;
            l1 = l1 * corr1 + sum1;
        }
        __syncthreads();
    }

    // ---- epilogue ----
    {
        float inv0 = 1.f / l0;
        float inv1 = 1.f / l1;
        __half* op0 = &attn[((size_t)b * Sq + r0g) * Eq + h * Dq];
        __half* op1 = &attn[((size_t)b * Sq + r1g) * Eq + h * Dq];
#pragma unroll
        for (int nd = 0; nd < 8; nd++) {
            int c0 = nd * 8 + 2 * j;
            *(__half2*)&op0[c0] = __floats2half2_rn(od[nd][0] * inv0, od[nd][1] * inv0);
            *(__half2*)&op1[c0] = __floats2half2_rn(od[nd][2] * inv1, od[nd][3] * inv1);
        }
    }
}

// ---------------------------------------------------------------------------
extern "C" void kernel_launch(void* const* d_in, const int* in_sizes, int n_in,
                              void* d_out, int out_size)
{
    const float* x     = (const float*)d_in[0];
    const float* w_qkv = (const float*)d_in[1];
    const float* w_out = (const float*)d_in[2];
    const float* fcos  = (const float*)d_in[3];
    const float* fsin  = (const float*)d_in[4];
    float* out = (float*)d_out;

    __half *qkv, *attn, *xh, *wqkvh, *wouth;
    cudaGetSymbolAddress((void**)&qkv, g_qkv);
    cudaGetSymbolAddress((void**)&attn, g_attn);
    cudaGetSymbolAddress((void**)&xh, g_xh);
    cudaGetSymbolAddress((void**)&wqkvh, g_wqkvh);
    cudaGetSymbolAddress((void**)&wouth, g_wouth);

    cudaFuncSetAttribute(gemm_f16<__half>,
                         cudaFuncAttributeMaxDynamicSharedMemorySize, GEMM_SMEM);
    cudaFuncSetAttribute(gemm_f16<float>,
                         cudaFuncAttributeMaxDynamicSharedMemorySize, GEMM_SMEM);
    cudaFuncSetAttribute(flash_attn_f16,
                         cudaFuncAttributeMaxDynamicSharedMemorySize, FA_SMEM);

    // 0) merged fp16 conversion of all GEMM inputs (one launch)
    {
        int n4 = N4X + N4Q + N4O;
        convert_all_kernel<<<(n4 + 255) / 256, 256>>>(x, xh, w_qkv, wqkvh,
                                                      w_out, wouth);
    }

    // 1) QKV projection -> fp16 qkv
    gemm_f16<__half><<<dim3(3 * Eq / GT_N, Bq * Sq / GT_M), 256, GEMM_SMEM>>>(
        xh, wqkvh, qkv, Bq * Sq, 3 * Eq, Eq);

    // 1b) in-place RoPE on Q (pre-scaled with log2e) and K
    {
        int n = Bq * Sq * Eq / 2;
        rope_qk_kernel<<<(n + 255) / 256, 256>>>(qkv, fcos, fsin);
    }

    // 2) causal flash attention (fp16 mma, exp2 softmax, heavy-first)
    flash_attn_f16<<<dim3(Sq / 128, Bq * Hq), 256, FA_SMEM>>>(qkv, attn);

    // 3) output projection -> fp32 out
    gemm_f16<float><<<dim3(Eq / GT_N, Bq * Sq / GT_M), 256, GEMM_SMEM>>>(
        attn, wouth, out, Bq * Sq, Eq, Eq);
}